// round 7
// baseline (speedup 1.0000x reference)
#include <cuda_runtime.h>
#include <cuda_fp16.h>
#include <cstdint>

// Problem constants (B=64, S=1024, D=768, R=4)
#define DD    768
#define ND    2304
#define RR    4
#define MTOT  65536

// GEMM tiling
#define BM 128
#define BN 128
#define BK 32
#define NKT (DD / BK)        // 24
#define STAGES 4

// smem stage layout: padded rows of 40 halves (80 B) for conflict-free ldmatrix
#define ROWB   80
#define MAT_B  (128 * ROWB)  // 10240 bytes per matrix tile
#define A_T    0
#define B_T    (MAT_B)
#define STG    (2 * MAT_B)   // 20480
#define SMEM_TOTAL (STAGES * STG)  // 81920

// prep kernel split
#define NCONV_BLK ((MTOT * DD / 4) / 256)   // 49152
#define NFOLD_BLK ((ND * DD + 255) / 256)   // 6912

// Static device scratch (no runtime allocation allowed)
__device__ __align__(128) __half g_X[(size_t)MTOT * DD];
__device__ __align__(128) __half g_W[(size_t)ND * DD];

// ---------------------------------------------------------------------------
// PTX helpers (baseline ISA only — safe under compute_103 virtual arch)
// ---------------------------------------------------------------------------
__device__ __forceinline__ uint32_t smem_u32(const void* p) {
    uint32_t a;
    asm("{ .reg .u64 t; cvta.to.shared.u64 t, %1; cvt.u32.u64 %0, t; }"
        : "=r"(a) : "l"(p));
    return a;
}

#define CPA(saddr, gaddr) \
    asm volatile("cp.async.cg.shared.global [%0], [%1], 16;" \
                 :: "r"(saddr), "l"(gaddr))

#define CP_COMMIT() asm volatile("cp.async.commit_group;" ::: "memory")
#define CP_WAIT2()  asm volatile("cp.async.wait_group 2;" ::: "memory")

#define LDSM4(r, addr)                                                        \
    asm volatile("ldmatrix.sync.aligned.m8n8.x4.shared.b16 {%0,%1,%2,%3}, [%4];" \
                 : "=r"((r)[0]), "=r"((r)[1]), "=r"((r)[2]), "=r"((r)[3])     \
                 : "r"(addr))

// fp16-accumulate MMA: D(f16x2 pair) = A*B + 0   (fresh chunk each call)
#define MMA16(d0, d1, a, b0, b1)                                              \
    asm volatile("mma.sync.aligned.m16n8k16.row.col.f16.f16.f16.f16 "         \
                 "{%0,%1},{%2,%3,%4,%5},{%6,%7},{%8,%9};"                     \
                 : "=r"(d0), "=r"(d1)                                         \
                 : "r"((a)[0]), "r"((a)[1]), "r"((a)[2]), "r"((a)[3]),        \
                   "r"(b0), "r"(b1), "r"(0u), "r"(0u))

// promote one f16x2 chunk pair into 4 fp32 accumulators
#define PROMOTE(c, d0, d1) do {                                               \
    float2 _p0 = __half22float2(*reinterpret_cast<const __half2*>(&(d0)));    \
    float2 _p1 = __half22float2(*reinterpret_cast<const __half2*>(&(d1)));    \
    (c)[0] += _p0.x; (c)[1] += _p0.y;                                         \
    (c)[2] += _p1.x; (c)[3] += _p1.y;                                         \
} while (0)

// ---------------------------------------------------------------------------
// Kernel 0 (fused prep): blocks [0, NCONV_BLK): X fp32 -> fp16
//                        blocks [NCONV_BLK, +NFOLD_BLK): LoRA-fold W -> fp16
// ---------------------------------------------------------------------------
__global__ void prep(const float4* __restrict__ X,
                     const float* __restrict__ W,
                     const float* __restrict__ Aq, const float* __restrict__ Bq,
                     const float* __restrict__ Av, const float* __restrict__ Bv,
                     const float* __restrict__ s0p) {
    if (blockIdx.x < NCONV_BLK) {
        size_t i = (size_t)blockIdx.x * blockDim.x + threadIdx.x;
        float4 v = X[i];
        __half2* ph = reinterpret_cast<__half2*>(g_X) + i * 2;
        ph[0] = __floats2half2_rn(v.x, v.y);
        ph[1] = __floats2half2_rn(v.z, v.w);
    } else {
        int idx = (blockIdx.x - NCONV_BLK) * blockDim.x + threadIdx.x;
        if (idx >= ND * DD) return;
        int e = idx / DD;
        int d = idx - e * DD;
        float v = W[idx];
        float s = s0p[0];
        if (e < DD) {
            float acc = 0.f;
#pragma unroll
            for (int r = 0; r < RR; r++) acc = fmaf(Bq[e * RR + r], Aq[r * DD + d], acc);
            v = fmaf(s, acc, v);
        } else if (e >= 2 * DD) {
            int e2 = e - 2 * DD;
            float acc = 0.f;
#pragma unroll
            for (int r = 0; r < RR; r++) acc = fmaf(Bv[e2 * RR + r], Av[r * DD + d], acc);
            v = fmaf(s, acc, v);
        }
        g_W[idx] = __float2half(v);
    }
}

// ---------------------------------------------------------------------------
// Kernel 1: fp16 mma.sync GEMM, fp16 per-chunk accumulate + fp32 promote.
//   Out[M, ND] = X @ W^T + bias
//   128x128x32 CTA tile, 8 warps (2x4), 64x32 warp tile, 4-stage cp.async.
//   2 CTAs/SM (80 KB smem each).
// ---------------------------------------------------------------------------
__global__ void __launch_bounds__(256, 2) gemm_mma(
    const float* __restrict__ bias, float* __restrict__ Out) {
    extern __shared__ char smem[];
    const uint32_t sb = smem_u32(smem);

    const int tid  = threadIdx.x;
    const int wid  = tid >> 5;
    const int lane = tid & 31;
    const int wm   = wid >> 2;          // 0..1  (64 rows each)
    const int wn   = wid & 3;           // 0..3  (32 cols each)
    const int n0   = blockIdx.x * BN;
    const int m0   = blockIdx.y * BM;

    // global load mapping: 512 16B chunks per matrix tile, 2 per thread
    const int r0c = tid >> 2;           // row for chunk 0 (0..63)
    const int cc  = tid & 3;            // 16B column (0..3)

    float acc[4][4][4];
#pragma unroll
    for (int i = 0; i < 4; i++)
#pragma unroll
        for (int j = 0; j < 4; j++)
#pragma unroll
            for (int q = 0; q < 4; q++) acc[i][j][q] = 0.f;

    // ---- stage loader ----
    auto load_stage = [&](int kt, int buf) {
        const uint32_t st = sb + buf * STG;
#pragma unroll
        for (int i = 0; i < 2; i++) {
            const int row = r0c + i * 64;
            const uint32_t so = st + row * ROWB + cc * 16;
            const size_t ga = (size_t)(m0 + row) * DD + kt * BK + cc * 8;
            const size_t gb = (size_t)(n0 + row) * DD + kt * BK + cc * 8;
            CPA(so + A_T, (const char*)(g_X + ga));
            CPA(so + B_T, (const char*)(g_W + gb));
        }
    };

    load_stage(0, 0); CP_COMMIT();
    load_stage(1, 1); CP_COMMIT();
    load_stage(2, 2); CP_COMMIT();

    // per-lane ldmatrix address pieces
    const int lrow = lane & 15;
    const int lhal = (lane >> 4) << 4;  // 0 or 16 bytes (8-col half)

    for (int kt = 0; kt < NKT; kt++) {
        const int buf = kt % STAGES;
        CP_WAIT2();
        __syncthreads();
        if (kt + 3 < NKT) load_stage(kt + 3, (kt + 3) % STAGES);
        CP_COMMIT();

        const uint32_t st = sb + buf * STG;
        const uint32_t abase = st + (wm * 64 + lrow) * ROWB + lhal;
        const uint32_t bbase = st + (wn * 32 + lrow) * ROWB + lhal;

#pragma unroll
        for (int kk = 0; kk < 2; kk++) {
            uint32_t aw[4][4], bw[2][4];
#pragma unroll
            for (int ti = 0; ti < 4; ti++)
                LDSM4(aw[ti], abase + A_T + ti * (16 * ROWB) + kk * 32);
#pragma unroll
            for (int tj = 0; tj < 2; tj++)
                LDSM4(bw[tj], bbase + B_T + tj * (16 * ROWB) + kk * 32);
#pragma unroll
            for (int ti = 0; ti < 4; ti++) {
#pragma unroll
                for (int nj = 0; nj < 4; nj++) {
                    const int tj = nj >> 1, o = nj & 1;
                    uint32_t d0, d1;
                    MMA16(d0, d1, aw[ti], bw[tj][o], bw[tj][o + 2]);
                    PROMOTE(acc[ti][nj], d0, d1);
                }
            }
        }
        __syncthreads();
    }

    // ---- epilogue: bias + store ----
    const int orow_base = m0 + wm * 64 + (lane >> 2);
    const int ocol_base = n0 + wn * 32 + (lane & 3) * 2;
#pragma unroll
    for (int ti = 0; ti < 4; ti++) {
        const int r0 = orow_base + ti * 16;
#pragma unroll
        for (int nj = 0; nj < 4; nj++) {
            const int c = ocol_base + nj * 8;
            const float2 bs = *reinterpret_cast<const float2*>(bias + c);
            float2 v0, v1;
            v0.x = acc[ti][nj][0] + bs.x;
            v0.y = acc[ti][nj][1] + bs.y;
            v1.x = acc[ti][nj][2] + bs.x;
            v1.y = acc[ti][nj][3] + bs.y;
            *reinterpret_cast<float2*>(Out + (size_t)r0 * ND + c) = v0;
            *reinterpret_cast<float2*>(Out + (size_t)(r0 + 8) * ND + c) = v1;
        }
    }
}

// ---------------------------------------------------------------------------
// Launch.  Inputs (metadata order): x, W_qkv, b_qkv, A_q, B_q, A_v, B_v, s0
// ---------------------------------------------------------------------------
extern "C" void kernel_launch(void* const* d_in, const int* in_sizes, int n_in,
                              void* d_out, int out_size) {
    const float* x  = (const float*)d_in[0];
    const float* W  = (const float*)d_in[1];
    const float* b  = (const float*)d_in[2];
    const float* Aq = (const float*)d_in[3];
    const float* Bq = (const float*)d_in[4];
    const float* Av = (const float*)d_in[5];
    const float* Bv = (const float*)d_in[6];
    const float* s0 = (const float*)d_in[7];
    float* out = (float*)d_out;

    prep<<<NCONV_BLK + NFOLD_BLK, 256>>>((const float4*)x, W, Aq, Bq, Av, Bv, s0);

    static bool attr_set = false;
    if (!attr_set) {
        cudaFuncSetAttribute(gemm_mma,
                             cudaFuncAttributeMaxDynamicSharedMemorySize,
                             SMEM_TOTAL);
        attr_set = true;
    }
    dim3 grid(ND / BN, MTOT / BM);      // (18, 512); x-fast => X tile L2 reuse
    gemm_mma<<<grid, 256, SMEM_TOTAL>>>(b, out);
}